// round 11
// baseline (speedup 1.0000x reference)
#include <cuda_runtime.h>

// CubECLayr: Euler characteristic curve of sublevel cubical complex.
// x: (64,3,256,256) f32 -> out: (192,32) f32.
//
// Owner attribution (one signed weight per pixel), sign-mask compares
// ((a>b) <=> sign(b-a) as -1/0, NaN-free), shared compares between incident
// pixels, magic-FFMA binning, REDS histogram, branchless lane edges, mod-3
// row rotation. This round: sign extraction via mul.hi.s32 (IMAD.HI, fma
// pipe) instead of SHF (alu pipe) to rebalance the 50%/13% alu/fma split.

#define TPB 64
#define RPW 8
#define NB  32          // data in [0,1) => bins 0..31 only

// mask = -1 iff a > b, else 0.  (2*x)>>32 == x>>31 arithmetic, exact for all
// int32; IMAD.HI runs on the fma pipe, unlike SHF (alu pipe).
__device__ __forceinline__ int MGT(float a, float b) {
    int r;
    asm("mul.hi.s32 %0, %1, 2;" : "=r"(r) : "r"(__float_as_int(b - a)));
    return r;
}

__global__ void ecc_zero(float* __restrict__ out) {
    int i = blockIdx.x * blockDim.x + threadIdx.x;
    if (i < 192 * 32) out[i] = 0.0f;
}

__global__ __launch_bounds__(TPB, 12) void ecc_main(const float* __restrict__ x,
                                                    float* __restrict__ out) {
    __shared__ int sh[NB * TPB];   // h[k][tid], stride 64 -> bank=tid%32 (conflict-free)
    __shared__ int red[NB];

    const int tid  = threadIdx.x;
    const int lane = tid & 31;
    const int wid  = tid >> 5;
    const int img  = blockIdx.x >> 4;     // 192 images
    const int band = blockIdx.x & 15;     // 16 bands of 16 rows
    const int R0   = band * 16 + wid * RPW;
    const float* __restrict__ base = x + (size_t)img * 65536 + (size_t)R0 * 256 + lane * 8;
    char* const hb = (char*)sh + tid * 4; // per-thread histogram column base

#pragma unroll
    for (int k = 0; k < NB; ++k) sh[(k << 6) + tid] = 0;
    __syncthreads();

    const float FINF = __int_as_float(0x7f800000);
    const unsigned FULL = 0xffffffffu;
    const bool lastStrip = (R0 + RPW) >= 256;
    const bool l0  = (lane == 0);
    const bool l31 = (lane == 31);

    float buf[3][8];               // rotating row buffers (row r in buf[r%3])
    float curL, curR;
    int P[8], D[8], A[8];          // carried up-row masks (v, diag, anti-diag)
    int pdm1, pa8;

    // ---- load rows R0 -> buf[0], R0+1 -> buf[1] ----
    {
        float4 a4 = *(const float4*)(base);
        float4 b4 = *(const float4*)(base + 4);
        buf[0][0]=a4.x; buf[0][1]=a4.y; buf[0][2]=a4.z; buf[0][3]=a4.w;
        buf[0][4]=b4.x; buf[0][5]=b4.y; buf[0][6]=b4.z; buf[0][7]=b4.w;
    }
    {
        float4 a4 = *(const float4*)(base + 256);
        float4 b4 = *(const float4*)(base + 256 + 4);
        buf[1][0]=a4.x; buf[1][1]=a4.y; buf[1][2]=a4.z; buf[1][3]=a4.w;
        buf[1][4]=b4.x; buf[1][5]=b4.y; buf[1][6]=b4.z; buf[1][7]=b4.w;
    }
    curL = __shfl_up_sync(FULL, buf[0][7], 1);   curL = l0  ? FINF : curL;
    curR = __shfl_down_sync(FULL, buf[0][0], 1); curR = l31 ? FINF : curR;

    // ---- carried masks from row R0-1 ----
    if (R0 > 0) {
        float pr[8];
        float4 a4 = *(const float4*)(base - 256);
        float4 b4 = *(const float4*)(base - 256 + 4);
        pr[0]=a4.x; pr[1]=a4.y; pr[2]=a4.z; pr[3]=a4.w;
        pr[4]=b4.x; pr[5]=b4.y; pr[6]=b4.z; pr[7]=b4.w;
        float prL = __shfl_up_sync(FULL, pr[7], 1);   prL = l0  ? FINF : prL;
        float prR = __shfl_down_sync(FULL, pr[0], 1); prR = l31 ? FINF : prR;
#pragma unroll
        for (int c = 0; c < 8; ++c) {
            P[c] = MGT(buf[0][c], pr[c]);
            D[c] = MGT((c < 7) ? buf[0][c + 1] : curR, pr[c]);
            A[c] = (c > 0) ? MGT(buf[0][c - 1], pr[c]) : 0;
        }
        pdm1 = MGT(buf[0][0], prL);
        pa8  = MGT(buf[0][7], prR);
    } else {
#pragma unroll
        for (int c = 0; c < 8; ++c) { P[c] = 0; D[c] = 0; A[c] = 0; }
        pdm1 = 0; pa8 = 0;
    }

    // ---- main loop: explicit rotation, all indices compile-time ----
#pragma unroll
    for (int i = 0; i < RPW; ++i) {
        const int i0 = i % 3;          // current row
        const int i1 = (i + 1) % 3;    // down row
        const int i2 = (i + 2) % 3;    // prefetch slot

        float dnL = __shfl_up_sync(FULL, buf[i1][7], 1);   dnL = l0  ? FINF : dnL;
        float dnR = __shfl_down_sync(FULL, buf[i1][0], 1); dnR = l31 ? FINF : dnR;

        // prefetch row R0+i+2 into buf[i2]
        if (i + 2 < RPW) {
            const float* p = base + (i + 2) * 256;
            float4 a4 = *(const float4*)(p);
            float4 b4 = *(const float4*)(p + 4);
            buf[i2][0]=a4.x; buf[i2][1]=a4.y; buf[i2][2]=a4.z; buf[i2][3]=a4.w;
            buf[i2][4]=b4.x; buf[i2][5]=b4.y; buf[i2][6]=b4.z; buf[i2][7]=b4.w;
        } else if (i + 2 == RPW) {
            if (!lastStrip) {
                const float* p = base + (i + 2) * 256;
                float4 a4 = *(const float4*)(p);
                float4 b4 = *(const float4*)(p + 4);
                buf[i2][0]=a4.x; buf[i2][1]=a4.y; buf[i2][2]=a4.z; buf[i2][3]=a4.w;
                buf[i2][4]=b4.x; buf[i2][5]=b4.y; buf[i2][6]=b4.z; buf[i2][7]=b4.w;
            } else {
#pragma unroll
                for (int c = 0; c < 8; ++c) buf[i2][c] = FINF;
            }
        }
        // i + 2 > RPW: slot never consumed; skip (compile-time).

        // horizontal masks for the current row (fresh SSA values)
        int h[8];
#pragma unroll
        for (int c = 0; c < 8; ++c)
            h[c] = MGT((c < 7) ? buf[i0][c + 1] : curR, buf[i0][c]);
        const int hm1 = MGT(buf[i0][0], curL);

        int pend = 0;
#pragma unroll
        for (int c = 0; c < 8; ++c) {
            const float m = buf[i0][c];
            const int v = MGT(buf[i1][c], m);
            const int d = MGT((c < 7) ? buf[i1][c + 1] : dnR, m);
            const int a = MGT((c > 0) ? buf[i1][c - 1] : dnL, m);

            const int gl  = (c > 0) ? h[c - 1] : hm1;
            const int nh  = h[c];
            const int gu  = P[c];
            const int gul = (c > 0) ? D[c - 1] : pdm1;
            const int gur = (c < 7) ? A[c + 1] : pa8;

            const int s1 = gl &  gu & gul;
            const int s2 = gu & ~nh & gur;
            const int s3 = gl & ~v  & ~a;
            const int s4 = ~nh & ~v & ~d;

            // w = gl+gu-nh-v-1 - (s1+s2+s3+s4), shaped for 4x 3-input adds
            const int t1 = (gl + gu) - nh;
            const int t2 = (s1 + s2) + s3;
            const int t3 = (t1 - v) - t2;
            const int w  = (t3 - s4) - 1;

            // bin = ceil(31*m) via exact FFMA.RU magic; byte off = bits*256 == k*256
            const unsigned bits = __float_as_uint(__fmaf_ru(m, 31.0f, 8388608.0f));
            atomicAdd((int*)(hb + bits * 256u), w);   // fire-and-forget REDS

            P[c] = v;
            if (c > 0) D[c - 1] = pend;
            pend = d;
            A[c] = a;
        }
        D[7] = pend;

        // halo masks for the next row (old curL/curR still live)
        pdm1 = MGT(buf[i1][0], curL);
        pa8  = MGT(buf[i1][7], curR);

        curL = dnL; curR = dnR;      // scalar renames
    }

    __syncthreads();

    // ---- block reduction: 2 half-sums per bin, lane-rotated (conflict-free) ----
    {
        const int b = tid >> 1, g = tid & 1;
        int s = 0;
#pragma unroll
        for (int j = 0; j < 32; ++j)
            s += sh[(b << 6) + (g << 5) + ((j + tid) & 31)];
        s += __shfl_xor_sync(FULL, s, 1);
        if (g == 0) red[b] = s;
    }
    __syncthreads();

    // ---- inclusive cumsum + exact integer-float atomic combine across bands ----
    if (tid < 32) {
        int acc = 0;
        for (int k = 0; k <= tid; ++k) acc += red[k];
        atomicAdd(&out[img * 32 + tid], (float)acc);
    }
}

extern "C" void kernel_launch(void* const* d_in, const int* in_sizes, int n_in,
                              void* d_out, int out_size) {
    const float* x = (const float*)d_in[0];
    float* out = (float*)d_out;
    ecc_zero<<<24, 256>>>(out);
    ecc_main<<<3072, TPB>>>(x, out);
}

// round 13
// speedup vs baseline: 1.2228x; 1.2228x over previous
#include <cuda_runtime.h>

// CubECLayr: Euler characteristic curve of sublevel cubical complex.
// x: (64,3,256,256) f32 -> out: (192,32) f32.
//
// Owner attribution (one signed weight per pixel). SIMD-within-register mask
// algebra: compare signs packed as 0x01 bytes (4 px/word via PRMT
// sign-replicate), square terms one LOP3 per 4 px, w computed as borrowless
// packed-byte arithmetic (bytes hold w+8; w = -gl-gu+nh+v+s1+s2+s3+s4-1).

#define TPB 64
#define RPW 8
#define NB  32          // data in [0,1) => bins 0..31 only

// Pack sign bits of 4 floats into one word as 0x01/0x00 bytes (byte c = f_c < 0).
__device__ __forceinline__ unsigned pack01(float f0, float f1, float f2, float f3) {
    unsigned t01, t23, p;
    asm("prmt.b32 %0, %1, %2, 0x00FB;" : "=r"(t01)
        : "r"(__float_as_uint(f0)), "r"(__float_as_uint(f1)));
    asm("prmt.b32 %0, %1, %2, 0x00FB;" : "=r"(t23)
        : "r"(__float_as_uint(f2)), "r"(__float_as_uint(f3)));
    asm("prmt.b32 %0, %1, %2, 0x5410;" : "=r"(p) : "r"(t01), "r"(t23));
    return p & 0x01010101u;
}

__device__ __forceinline__ unsigned signbit01(float f) {   // 1 iff f < 0
    return __float_as_uint(f) >> 31;
}

__global__ void ecc_zero(float* __restrict__ out) {
    int i = blockIdx.x * blockDim.x + threadIdx.x;
    if (i < 192 * 32) out[i] = 0.0f;
}

__global__ __launch_bounds__(TPB, 12) void ecc_main(const float* __restrict__ x,
                                                    float* __restrict__ out) {
    __shared__ int sh[NB * TPB];   // h[k][tid], stride 64 -> conflict-free
    __shared__ int red[NB];

    const int tid  = threadIdx.x;
    const int lane = tid & 31;
    const int wid  = tid >> 5;
    const int img  = blockIdx.x >> 4;     // 192 images
    const int band = blockIdx.x & 15;     // 16 bands of 16 rows
    const int R0   = band * 16 + wid * RPW;
    const float* __restrict__ base = x + (size_t)img * 65536 + (size_t)R0 * 256 + lane * 8;
    char* const hb = (char*)sh + tid * 4;

#pragma unroll
    for (int k = 0; k < NB; ++k) sh[(k << 6) + tid] = 0;
    __syncthreads();

    const float FINF = __int_as_float(0x7f800000);
    const unsigned FULL = 0xffffffffu;
    const unsigned ONE = 0x01010101u;
    const bool lastStrip = (R0 + RPW) >= 256;
    const bool l0  = (lane == 0);
    const bool l31 = (lane == 31);

    float buf[3][8];               // rotating row buffers (row r in buf[r%3])
    float curL, curR;
    unsigned PV0, PV1, PD0, PD1, PA0, PA1;   // packed carried masks (v, diag, anti)
    unsigned pdm1b, pa8b;                    // boundary bits (0/1)

    // ---- load rows R0 -> buf[0], R0+1 -> buf[1] ----
    {
        float4 a4 = *(const float4*)(base);
        float4 b4 = *(const float4*)(base + 4);
        buf[0][0]=a4.x; buf[0][1]=a4.y; buf[0][2]=a4.z; buf[0][3]=a4.w;
        buf[0][4]=b4.x; buf[0][5]=b4.y; buf[0][6]=b4.z; buf[0][7]=b4.w;
    }
    {
        float4 a4 = *(const float4*)(base + 256);
        float4 b4 = *(const float4*)(base + 256 + 4);
        buf[1][0]=a4.x; buf[1][1]=a4.y; buf[1][2]=a4.z; buf[1][3]=a4.w;
        buf[1][4]=b4.x; buf[1][5]=b4.y; buf[1][6]=b4.z; buf[1][7]=b4.w;
    }
    curL = __shfl_up_sync(FULL, buf[0][7], 1);   curL = l0  ? FINF : curL;
    curR = __shfl_down_sync(FULL, buf[0][0], 1); curR = l31 ? FINF : curR;

    // ---- carried packed masks from row R0-1 ----
    if (R0 > 0) {
        float pr[8];
        float4 a4 = *(const float4*)(base - 256);
        float4 b4 = *(const float4*)(base - 256 + 4);
        pr[0]=a4.x; pr[1]=a4.y; pr[2]=a4.z; pr[3]=a4.w;
        pr[4]=b4.x; pr[5]=b4.y; pr[6]=b4.z; pr[7]=b4.w;
        float prL = __shfl_up_sync(FULL, pr[7], 1);   prL = l0  ? FINF : prL;
        float prR = __shfl_down_sync(FULL, pr[0], 1); prR = l31 ? FINF : prR;
        // PV[c] = cur[c] > pr[c]
        PV0 = pack01(pr[0]-buf[0][0], pr[1]-buf[0][1], pr[2]-buf[0][2], pr[3]-buf[0][3]);
        PV1 = pack01(pr[4]-buf[0][4], pr[5]-buf[0][5], pr[6]-buf[0][6], pr[7]-buf[0][7]);
        // PD[c] = cur[c+1] > pr[c] (c=7: curR)
        PD0 = pack01(pr[0]-buf[0][1], pr[1]-buf[0][2], pr[2]-buf[0][3], pr[3]-buf[0][4]);
        PD1 = pack01(pr[4]-buf[0][5], pr[5]-buf[0][6], pr[6]-buf[0][7], pr[7]-curR);
        // PA[c] = cur[c-1] > pr[c] (c=0 byte unused)
        PA0 = pack01(1.0f,            pr[1]-buf[0][0], pr[2]-buf[0][1], pr[3]-buf[0][2]);
        PA1 = pack01(pr[4]-buf[0][3], pr[5]-buf[0][4], pr[6]-buf[0][5], pr[7]-buf[0][6]);
        pdm1b = signbit01(prL - buf[0][0]);   // cur[0] > prL
        pa8b  = signbit01(prR - buf[0][7]);   // cur[7] > prR
    } else {
        PV0 = PV1 = PD0 = PD1 = PA0 = PA1 = 0u;
        pdm1b = 0u; pa8b = 0u;
    }

    // ---- main loop: explicit rotation, all indices compile-time ----
#pragma unroll
    for (int i = 0; i < RPW; ++i) {
        const int i0 = i % 3;          // current row
        const int i1 = (i + 1) % 3;    // down row
        const int i2 = (i + 2) % 3;    // prefetch slot

        float dnL = __shfl_up_sync(FULL, buf[i1][7], 1);   dnL = l0  ? FINF : dnL;
        float dnR = __shfl_down_sync(FULL, buf[i1][0], 1); dnR = l31 ? FINF : dnR;

        // prefetch row R0+i+2 into buf[i2]
        if (i + 2 < RPW) {
            const float* p = base + (i + 2) * 256;
            float4 a4 = *(const float4*)(p);
            float4 b4 = *(const float4*)(p + 4);
            buf[i2][0]=a4.x; buf[i2][1]=a4.y; buf[i2][2]=a4.z; buf[i2][3]=a4.w;
            buf[i2][4]=b4.x; buf[i2][5]=b4.y; buf[i2][6]=b4.z; buf[i2][7]=b4.w;
        } else if (i + 2 == RPW) {
            if (!lastStrip) {
                const float* p = base + (i + 2) * 256;
                float4 a4 = *(const float4*)(p);
                float4 b4 = *(const float4*)(p + 4);
                buf[i2][0]=a4.x; buf[i2][1]=a4.y; buf[i2][2]=a4.z; buf[i2][3]=a4.w;
                buf[i2][4]=b4.x; buf[i2][5]=b4.y; buf[i2][6]=b4.z; buf[i2][7]=b4.w;
            } else {
#pragma unroll
                for (int c = 0; c < 8; ++c) buf[i2][c] = FINF;
            }
        }

        // ---- packed compare masks for this row (byte c of word = pixel c) ----
        // NH[c] = right > cur[c]
        const unsigned NH0 = pack01(buf[i0][0]-buf[i0][1], buf[i0][1]-buf[i0][2],
                                    buf[i0][2]-buf[i0][3], buf[i0][3]-buf[i0][4]);
        const unsigned NH1 = pack01(buf[i0][4]-buf[i0][5], buf[i0][5]-buf[i0][6],
                                    buf[i0][6]-buf[i0][7], buf[i0][7]-curR);
        // V[c] = dn[c] > cur[c]
        const unsigned V0 = pack01(buf[i0][0]-buf[i1][0], buf[i0][1]-buf[i1][1],
                                   buf[i0][2]-buf[i1][2], buf[i0][3]-buf[i1][3]);
        const unsigned V1 = pack01(buf[i0][4]-buf[i1][4], buf[i0][5]-buf[i1][5],
                                   buf[i0][6]-buf[i1][6], buf[i0][7]-buf[i1][7]);
        // Dm[c] = dn[c+1] > cur[c]  (c=7: dnR)
        const unsigned D0 = pack01(buf[i0][0]-buf[i1][1], buf[i0][1]-buf[i1][2],
                                   buf[i0][2]-buf[i1][3], buf[i0][3]-buf[i1][4]);
        const unsigned D1 = pack01(buf[i0][4]-buf[i1][5], buf[i0][5]-buf[i1][6],
                                   buf[i0][6]-buf[i1][7], buf[i0][7]-dnR);
        // Am[c] = dn[c-1] > cur[c]  (c=0: dnL)
        const unsigned A0 = pack01(buf[i0][0]-dnL,        buf[i0][1]-buf[i1][0],
                                   buf[i0][2]-buf[i1][1], buf[i0][3]-buf[i1][2]);
        const unsigned A1 = pack01(buf[i0][4]-buf[i1][3], buf[i0][5]-buf[i1][4],
                                   buf[i0][6]-buf[i1][5], buf[i0][7]-buf[i1][6]);

        const unsigned hm1b = signbit01(curL - buf[i0][0]);   // cur[0] > curL

        // ---- shifted vectors (boundary bytes inserted via PRMT) ----
        const unsigned GL0  = __byte_perm(NH0, hm1b,  0x2104);
        const unsigned GL1  = __byte_perm(NH0, NH1,   0x6543);
        const unsigned GUL0 = __byte_perm(PD0, pdm1b, 0x2104);
        const unsigned GUL1 = __byte_perm(PD0, PD1,   0x6543);
        const unsigned GUR0 = __byte_perm(PA0, PA1,   0x4321);
        const unsigned GUR1 = __byte_perm(PA1, pa8b,  0x4321);
        const unsigned GU0  = PV0, GU1 = PV1;

        // ---- packed w+8 per byte:
        //      w = -gl - gu + nh + v + s1+s2+s3+s4 - 1
        //      W  = (NH+V+s1) + (s2+s3+s4) + (7 - GL - GU); byte ranges [5..13]
        unsigned W0, W1;
        {
            const unsigned s1 = GL0 & GU0 & GUL0;
            const unsigned s2 = GU0 & GUR0 & ~NH0;
            const unsigned s3 = GL0 & ~V0 & ~A0;
            const unsigned t  = ONE & ~NH0 & ~V0;
            const unsigned s4 = t & ~D0;
            const unsigned T1 = NH0 + V0 + s1;
            const unsigned T2 = s2 + s3 + s4;
            W0 = T1 + T2 + (0x07070707u - GL0 - GU0);
        }
        {
            const unsigned s1 = GL1 & GU1 & GUL1;
            const unsigned s2 = GU1 & GUR1 & ~NH1;
            const unsigned s3 = GL1 & ~V1 & ~A1;
            const unsigned t  = ONE & ~NH1 & ~V1;
            const unsigned s4 = t & ~D1;
            const unsigned T1 = NH1 + V1 + s1;
            const unsigned T2 = s2 + s3 + s4;
            W1 = T1 + T2 + (0x07070707u - GL1 - GU1);
        }

        // ---- scatter: per pixel extract byte, debias, REDS into histogram ----
#pragma unroll
        for (int c = 0; c < 8; ++c) {
            const unsigned Wj = (c < 4) ? W0 : W1;
            const int w = (int)__byte_perm(Wj, 0u, 0x4440 + (c & 3)) - 8;
            const float m = buf[i0][c];
            const unsigned bits = __float_as_uint(__fmaf_ru(m, 31.0f, 8388608.0f));
            atomicAdd((int*)(hb + bits * 256u), w);
        }

        // ---- carries for next row ----
        PV0 = V0; PV1 = V1;
        PD0 = D0; PD1 = D1;
        PA0 = A0; PA1 = A1;
        pdm1b = signbit01(curL - buf[i1][0]);   // dn[0] > curL
        pa8b  = signbit01(curR - buf[i1][7]);   // dn[7] > curR
        curL = dnL; curR = dnR;
    }

    __syncthreads();

    // ---- block reduction: 2 half-sums per bin, lane-rotated (conflict-free) ----
    {
        const int b = tid >> 1, g = tid & 1;
        int s = 0;
#pragma unroll
        for (int j = 0; j < 32; ++j)
            s += sh[(b << 6) + (g << 5) + ((j + tid) & 31)];
        s += __shfl_xor_sync(FULL, s, 1);
        if (g == 0) red[b] = s;
    }
    __syncthreads();

    // ---- inclusive cumsum + exact integer-float atomic combine across bands ----
    if (tid < 32) {
        int acc = 0;
        for (int k = 0; k <= tid; ++k) acc += red[k];
        atomicAdd(&out[img * 32 + tid], (float)acc);
    }
}

extern "C" void kernel_launch(void* const* d_in, const int* in_sizes, int n_in,
                              void* d_out, int out_size) {
    const float* x = (const float*)d_in[0];
    float* out = (float*)d_out;
    ecc_zero<<<24, 256>>>(out);
    ecc_main<<<3072, TPB>>>(x, out);
}

// round 15
// speedup vs baseline: 1.3409x; 1.0966x over previous
#include <cuda_runtime.h>

// CubECLayr: Euler characteristic curve of sublevel cubical complex.
// x: (64,3,256,256) f32 -> out: (192,32) f32.
//
// Owner attribution (one signed weight per pixel). SIMD-within-register mask
// algebra: compare signs packed per 4 px via PRMT sign-replicate. NH/V packs
// 0x01-byte clean (summed); D/A packs 0xFF sign-form (LOP3-only). W built
// with bias 127 (borrowless), XOR 0x80 -> signed bytes; per-pixel w extracted
// with ONE sign-extending raw prmt.b32 (the __byte_perm intrinsic does NOT
// honor the sign-replicate mode — that was R14's bug).

#define TPB 64
#define RPW 8
#define NB  32          // data in [0,1) => bins 0..31 only

// 0x01/0x00 bytes (byte c = f_c < 0) — for masks that get SUMMED.
__device__ __forceinline__ unsigned pack01(float f0, float f1, float f2, float f3) {
    unsigned t01, t23, p;
    asm("prmt.b32 %0, %1, %2, 0x00FB;" : "=r"(t01)
        : "r"(__float_as_uint(f0)), "r"(__float_as_uint(f1)));
    asm("prmt.b32 %0, %1, %2, 0x00FB;" : "=r"(t23)
        : "r"(__float_as_uint(f2)), "r"(__float_as_uint(f3)));
    asm("prmt.b32 %0, %1, %2, 0x5410;" : "=r"(p) : "r"(t01), "r"(t23));
    return p & 0x01010101u;
}

// 0xFF/0x00 bytes — for masks consumed only by LOP3 (D, A, their carries).
__device__ __forceinline__ unsigned packFF(float f0, float f1, float f2, float f3) {
    unsigned t01, t23, p;
    asm("prmt.b32 %0, %1, %2, 0x00FB;" : "=r"(t01)
        : "r"(__float_as_uint(f0)), "r"(__float_as_uint(f1)));
    asm("prmt.b32 %0, %1, %2, 0x00FB;" : "=r"(t23)
        : "r"(__float_as_uint(f2)), "r"(__float_as_uint(f3)));
    asm("prmt.b32 %0, %1, %2, 0x5410;" : "=r"(p) : "r"(t01), "r"(t23));
    return p;
}

__device__ __forceinline__ unsigned signbit01(float f) {   // 0x00000001 iff f < 0
    return __float_as_uint(f) >> 31;
}
__device__ __forceinline__ unsigned signbitFF(float f) {   // 0xFFFFFFFF iff f < 0
    return (unsigned)(__float_as_int(f) >> 31);
}

// Sign-extended byte extract via raw prmt (sign-replicate mode).
__device__ __forceinline__ int sext_byte(unsigned x, int sel) {
    int r;
    asm("prmt.b32 %0, %1, 0, %2;" : "=r"(r) : "r"(x), "r"(sel));
    return r;
}

__global__ void ecc_zero(float* __restrict__ out) {
    int i = blockIdx.x * blockDim.x + threadIdx.x;
    if (i < 192 * 32) out[i] = 0.0f;
}

__global__ __launch_bounds__(TPB, 12) void ecc_main(const float* __restrict__ x,
                                                    float* __restrict__ out) {
    __shared__ int sh[NB * TPB];   // h[k][tid], stride 64 -> conflict-free
    __shared__ int red[NB];

    const int tid  = threadIdx.x;
    const int lane = tid & 31;
    const int wid  = tid >> 5;
    const int img  = blockIdx.x >> 4;     // 192 images
    const int band = blockIdx.x & 15;     // 16 bands of 16 rows
    const int R0   = band * 16 + wid * RPW;
    const float* __restrict__ base = x + (size_t)img * 65536 + (size_t)R0 * 256 + lane * 8;
    char* const hb = (char*)sh + tid * 4;

#pragma unroll
    for (int k = 0; k < NB; ++k) sh[(k << 6) + tid] = 0;
    __syncthreads();

    const float FINF = __int_as_float(0x7f800000);
    const unsigned FULL = 0xffffffffu;
    const unsigned ONE = 0x01010101u;
    const bool lastStrip = (R0 + RPW) >= 256;
    const bool l0  = (lane == 0);
    const bool l31 = (lane == 31);

    float buf[3][8];               // rotating row buffers (row r in buf[r%3])
    float curL, curR;
    unsigned PV0, PV1, PD0, PD1, PA0, PA1;   // carried masks (V clean; D/A FF-form)
    unsigned pdm1b, pa8b;                    // boundary (FF-form)

    // ---- load rows R0 -> buf[0], R0+1 -> buf[1] ----
    {
        float4 a4 = *(const float4*)(base);
        float4 b4 = *(const float4*)(base + 4);
        buf[0][0]=a4.x; buf[0][1]=a4.y; buf[0][2]=a4.z; buf[0][3]=a4.w;
        buf[0][4]=b4.x; buf[0][5]=b4.y; buf[0][6]=b4.z; buf[0][7]=b4.w;
    }
    {
        float4 a4 = *(const float4*)(base + 256);
        float4 b4 = *(const float4*)(base + 256 + 4);
        buf[1][0]=a4.x; buf[1][1]=a4.y; buf[1][2]=a4.z; buf[1][3]=a4.w;
        buf[1][4]=b4.x; buf[1][5]=b4.y; buf[1][6]=b4.z; buf[1][7]=b4.w;
    }
    curL = __shfl_up_sync(FULL, buf[0][7], 1);   curL = l0  ? FINF : curL;
    curR = __shfl_down_sync(FULL, buf[0][0], 1); curR = l31 ? FINF : curR;

    // ---- carried packed masks from row R0-1 ----
    if (R0 > 0) {
        float pr[8];
        float4 a4 = *(const float4*)(base - 256);
        float4 b4 = *(const float4*)(base - 256 + 4);
        pr[0]=a4.x; pr[1]=a4.y; pr[2]=a4.z; pr[3]=a4.w;
        pr[4]=b4.x; pr[5]=b4.y; pr[6]=b4.z; pr[7]=b4.w;
        float prL = __shfl_up_sync(FULL, pr[7], 1);   prL = l0  ? FINF : prL;
        float prR = __shfl_down_sync(FULL, pr[0], 1); prR = l31 ? FINF : prR;
        // PV[c] = cur[c] > pr[c]   (clean: summed as GU)
        PV0 = pack01(pr[0]-buf[0][0], pr[1]-buf[0][1], pr[2]-buf[0][2], pr[3]-buf[0][3]);
        PV1 = pack01(pr[4]-buf[0][4], pr[5]-buf[0][5], pr[6]-buf[0][6], pr[7]-buf[0][7]);
        // PD[c] = cur[c+1] > pr[c] (c=7: curR)  (FF-form: LOP3-only)
        PD0 = packFF(pr[0]-buf[0][1], pr[1]-buf[0][2], pr[2]-buf[0][3], pr[3]-buf[0][4]);
        PD1 = packFF(pr[4]-buf[0][5], pr[5]-buf[0][6], pr[6]-buf[0][7], pr[7]-curR);
        // PA[c] = cur[c-1] > pr[c] (c=0 byte unused)  (FF-form)
        PA0 = packFF(1.0f,            pr[1]-buf[0][0], pr[2]-buf[0][1], pr[3]-buf[0][2]);
        PA1 = packFF(pr[4]-buf[0][3], pr[5]-buf[0][4], pr[6]-buf[0][5], pr[7]-buf[0][6]);
        pdm1b = signbitFF(prL - buf[0][0]);   // cur[0] > prL
        pa8b  = signbitFF(prR - buf[0][7]);   // cur[7] > prR
    } else {
        PV0 = PV1 = PD0 = PD1 = PA0 = PA1 = 0u;
        pdm1b = 0u; pa8b = 0u;
    }

    // ---- main loop: explicit rotation, all indices compile-time ----
#pragma unroll
    for (int i = 0; i < RPW; ++i) {
        const int i0 = i % 3;          // current row
        const int i1 = (i + 1) % 3;    // down row
        const int i2 = (i + 2) % 3;    // prefetch slot

        float dnL = __shfl_up_sync(FULL, buf[i1][7], 1);   dnL = l0  ? FINF : dnL;
        float dnR = __shfl_down_sync(FULL, buf[i1][0], 1); dnR = l31 ? FINF : dnR;

        // prefetch row R0+i+2 into buf[i2]
        if (i + 2 < RPW) {
            const float* p = base + (i + 2) * 256;
            float4 a4 = *(const float4*)(p);
            float4 b4 = *(const float4*)(p + 4);
            buf[i2][0]=a4.x; buf[i2][1]=a4.y; buf[i2][2]=a4.z; buf[i2][3]=a4.w;
            buf[i2][4]=b4.x; buf[i2][5]=b4.y; buf[i2][6]=b4.z; buf[i2][7]=b4.w;
        } else if (i + 2 == RPW) {
            if (!lastStrip) {
                const float* p = base + (i + 2) * 256;
                float4 a4 = *(const float4*)(p);
                float4 b4 = *(const float4*)(p + 4);
                buf[i2][0]=a4.x; buf[i2][1]=a4.y; buf[i2][2]=a4.z; buf[i2][3]=a4.w;
                buf[i2][4]=b4.x; buf[i2][5]=b4.y; buf[i2][6]=b4.z; buf[i2][7]=b4.w;
            } else {
#pragma unroll
                for (int c = 0; c < 8; ++c) buf[i2][c] = FINF;
            }
        }

        // ---- packed compare masks (byte c = pixel c) ----
        // NH[c] = right > cur[c]   (clean: summed, carried as GL source)
        const unsigned NH0 = pack01(buf[i0][0]-buf[i0][1], buf[i0][1]-buf[i0][2],
                                    buf[i0][2]-buf[i0][3], buf[i0][3]-buf[i0][4]);
        const unsigned NH1 = pack01(buf[i0][4]-buf[i0][5], buf[i0][5]-buf[i0][6],
                                    buf[i0][6]-buf[i0][7], buf[i0][7]-curR);
        // V[c] = dn[c] > cur[c]    (clean: summed now, GU next row)
        const unsigned V0 = pack01(buf[i0][0]-buf[i1][0], buf[i0][1]-buf[i1][1],
                                   buf[i0][2]-buf[i1][2], buf[i0][3]-buf[i1][3]);
        const unsigned V1 = pack01(buf[i0][4]-buf[i1][4], buf[i0][5]-buf[i1][5],
                                   buf[i0][6]-buf[i1][6], buf[i0][7]-buf[i1][7]);
        // Dm[c] = dn[c+1] > cur[c]  (c=7: dnR)   (FF-form)
        const unsigned D0 = packFF(buf[i0][0]-buf[i1][1], buf[i0][1]-buf[i1][2],
                                   buf[i0][2]-buf[i1][3], buf[i0][3]-buf[i1][4]);
        const unsigned D1 = packFF(buf[i0][4]-buf[i1][5], buf[i0][5]-buf[i1][6],
                                   buf[i0][6]-buf[i1][7], buf[i0][7]-dnR);
        // Am[c] = dn[c-1] > cur[c]  (c=0: dnL)   (FF-form)
        const unsigned A0 = packFF(buf[i0][0]-dnL,        buf[i0][1]-buf[i1][0],
                                   buf[i0][2]-buf[i1][1], buf[i0][3]-buf[i1][2]);
        const unsigned A1 = packFF(buf[i0][4]-buf[i1][3], buf[i0][5]-buf[i1][4],
                                   buf[i0][6]-buf[i1][5], buf[i0][7]-buf[i1][6]);

        const unsigned hm1b = signbit01(curL - buf[i0][0]);   // clean (summed via GL)

        // ---- shifted vectors (boundary bytes via PRMT) ----
        const unsigned GL0  = __byte_perm(NH0, hm1b,  0x2104);   // clean
        const unsigned GL1  = __byte_perm(NH0, NH1,   0x6543);   // clean
        const unsigned GUL0 = __byte_perm(PD0, pdm1b, 0x2104);   // FF
        const unsigned GUL1 = __byte_perm(PD0, PD1,   0x6543);   // FF
        const unsigned GUR0 = __byte_perm(PA0, PA1,   0x4321);   // FF
        const unsigned GUR1 = __byte_perm(PA1, pa8b,  0x4321);   // FF
        const unsigned GU0  = PV0, GU1 = PV1;                    // clean

        // ---- packed signed-byte w:
        //      w = nh + v + s1+s2+s3+s4 - gl - gu - 1
        //      W128 byte = w + 128 (borrowless, bias 127); ^0x80 -> signed byte
        unsigned Ws0, Ws1;
        {
            const unsigned s1 = GL0 & GU0 & GUL0;
            const unsigned s2 = GU0 & GUR0 & ~NH0;
            const unsigned s3 = GL0 & ~V0 & ~A0;
            const unsigned t  = ONE & ~NH0 & ~V0;
            const unsigned s4 = t & ~D0;
            const unsigned T1 = NH0 + V0 + s1;
            const unsigned T2 = s2 + s3 + s4;
            Ws0 = (T1 + T2 + (0x7F7F7F7Fu - GL0 - GU0)) ^ 0x80808080u;
        }
        {
            const unsigned s1 = GL1 & GU1 & GUL1;
            const unsigned s2 = GU1 & GUR1 & ~NH1;
            const unsigned s3 = GL1 & ~V1 & ~A1;
            const unsigned t  = ONE & ~NH1 & ~V1;
            const unsigned s4 = t & ~D1;
            const unsigned T1 = NH1 + V1 + s1;
            const unsigned T2 = s2 + s3 + s4;
            Ws1 = (T1 + T2 + (0x7F7F7F7Fu - GL1 - GU1)) ^ 0x80808080u;
        }

        // ---- scatter: ONE sign-extending prmt per pixel (w directly), REDS ----
#pragma unroll
        for (int c = 0; c < 8; ++c) {
            const unsigned Wj = (c < 4) ? Ws0 : Ws1;
            const int w = sext_byte(Wj, 0x8880 + 0x1111 * (c & 3));
            const float m = buf[i0][c];
            const unsigned bits = __float_as_uint(__fmaf_ru(m, 31.0f, 8388608.0f));
            atomicAdd((int*)(hb + bits * 256u), w);
        }

        // ---- carries for next row ----
        PV0 = V0; PV1 = V1;
        PD0 = D0; PD1 = D1;
        PA0 = A0; PA1 = A1;
        pdm1b = signbitFF(curL - buf[i1][0]);   // dn[0] > curL
        pa8b  = signbitFF(curR - buf[i1][7]);   // dn[7] > curR
        curL = dnL; curR = dnR;
    }

    __syncthreads();

    // ---- block reduction: 2 half-sums per bin, lane-rotated (conflict-free) ----
    {
        const int b = tid >> 1, g = tid & 1;
        int s = 0;
#pragma unroll
        for (int j = 0; j < 32; ++j)
            s += sh[(b << 6) + (g << 5) + ((j + tid) & 31)];
        s += __shfl_xor_sync(FULL, s, 1);
        if (g == 0) red[b] = s;
    }
    __syncthreads();

    // ---- inclusive cumsum + exact integer-float atomic combine across bands ----
    if (tid < 32) {
        int acc = 0;
        for (int k = 0; k <= tid; ++k) acc += red[k];
        atomicAdd(&out[img * 32 + tid], (float)acc);
    }
}

extern "C" void kernel_launch(void* const* d_in, const int* in_sizes, int n_in,
                              void* d_out, int out_size) {
    const float* x = (const float*)d_in[0];
    float* out = (float*)d_out;
    ecc_zero<<<24, 256>>>(out);
    ecc_main<<<3072, TPB>>>(x, out);
}

// round 16
// speedup vs baseline: 1.3435x; 1.0019x over previous
#include <cuda_runtime.h>

// CubECLayr: Euler characteristic curve of sublevel cubical complex.
// x: (64,3,256,256) f32 -> out: (192,32) f32.
//
// Owner attribution (one signed weight per pixel). SIMD-within-register mask
// algebra: compare signs packed per 4 px via PRMT sign-replicate. NH/V packs
// 0x01-byte clean (summed); D/A packs 0xFF sign-form (LOP3-only). W built
// with bias 127 (borrowless), XOR 0x80 -> signed bytes; per-pixel w extracted
// with ONE sign-extending raw prmt.b32. R16: launch_bounds(64,14) for 28
// warps/SM; dropped the redundant post-init barrier (each thread zeroes only
// its own histogram column).

#define TPB 64
#define RPW 8
#define NB  32          // data in [0,1) => bins 0..31 only

// 0x01/0x00 bytes (byte c = f_c < 0) — for masks that get SUMMED.
__device__ __forceinline__ unsigned pack01(float f0, float f1, float f2, float f3) {
    unsigned t01, t23, p;
    asm("prmt.b32 %0, %1, %2, 0x00FB;" : "=r"(t01)
        : "r"(__float_as_uint(f0)), "r"(__float_as_uint(f1)));
    asm("prmt.b32 %0, %1, %2, 0x00FB;" : "=r"(t23)
        : "r"(__float_as_uint(f2)), "r"(__float_as_uint(f3)));
    asm("prmt.b32 %0, %1, %2, 0x5410;" : "=r"(p) : "r"(t01), "r"(t23));
    return p & 0x01010101u;
}

// 0xFF/0x00 bytes — for masks consumed only by LOP3 (D, A, their carries).
__device__ __forceinline__ unsigned packFF(float f0, float f1, float f2, float f3) {
    unsigned t01, t23, p;
    asm("prmt.b32 %0, %1, %2, 0x00FB;" : "=r"(t01)
        : "r"(__float_as_uint(f0)), "r"(__float_as_uint(f1)));
    asm("prmt.b32 %0, %1, %2, 0x00FB;" : "=r"(t23)
        : "r"(__float_as_uint(f2)), "r"(__float_as_uint(f3)));
    asm("prmt.b32 %0, %1, %2, 0x5410;" : "=r"(p) : "r"(t01), "r"(t23));
    return p;
}

__device__ __forceinline__ unsigned signbit01(float f) {   // 0x00000001 iff f < 0
    return __float_as_uint(f) >> 31;
}
__device__ __forceinline__ unsigned signbitFF(float f) {   // 0xFFFFFFFF iff f < 0
    return (unsigned)(__float_as_int(f) >> 31);
}

// Sign-extended byte extract via raw prmt (sign-replicate mode).
__device__ __forceinline__ int sext_byte(unsigned x, int sel) {
    int r;
    asm("prmt.b32 %0, %1, 0, %2;" : "=r"(r) : "r"(x), "r"(sel));
    return r;
}

__global__ void ecc_zero(float* __restrict__ out) {
    int i = blockIdx.x * blockDim.x + threadIdx.x;
    if (i < 192 * 32) out[i] = 0.0f;
}

__global__ __launch_bounds__(TPB, 14) void ecc_main(const float* __restrict__ x,
                                                    float* __restrict__ out) {
    __shared__ int sh[NB * TPB];   // h[k][tid], stride 64 -> conflict-free
    __shared__ int red[NB];

    const int tid  = threadIdx.x;
    const int lane = tid & 31;
    const int wid  = tid >> 5;
    const int img  = blockIdx.x >> 4;     // 192 images
    const int band = blockIdx.x & 15;     // 16 bands of 16 rows
    const int R0   = band * 16 + wid * RPW;
    const float* __restrict__ base = x + (size_t)img * 65536 + (size_t)R0 * 256 + lane * 8;
    char* const hb = (char*)sh + tid * 4;

    // Each thread zeroes exactly its own histogram column (the only column
    // its REDS ever target) — no barrier needed before the main loop.
#pragma unroll
    for (int k = 0; k < NB; ++k) sh[(k << 6) + tid] = 0;

    const float FINF = __int_as_float(0x7f800000);
    const unsigned FULL = 0xffffffffu;
    const unsigned ONE = 0x01010101u;
    const bool lastStrip = (R0 + RPW) >= 256;
    const bool l0  = (lane == 0);
    const bool l31 = (lane == 31);

    float buf[3][8];               // rotating row buffers (row r in buf[r%3])
    float curL, curR;
    unsigned PV0, PV1, PD0, PD1, PA0, PA1;   // carried masks (V clean; D/A FF-form)
    unsigned pdm1b, pa8b;                    // boundary (FF-form)

    // ---- load rows R0 -> buf[0], R0+1 -> buf[1] ----
    {
        float4 a4 = *(const float4*)(base);
        float4 b4 = *(const float4*)(base + 4);
        buf[0][0]=a4.x; buf[0][1]=a4.y; buf[0][2]=a4.z; buf[0][3]=a4.w;
        buf[0][4]=b4.x; buf[0][5]=b4.y; buf[0][6]=b4.z; buf[0][7]=b4.w;
    }
    {
        float4 a4 = *(const float4*)(base + 256);
        float4 b4 = *(const float4*)(base + 256 + 4);
        buf[1][0]=a4.x; buf[1][1]=a4.y; buf[1][2]=a4.z; buf[1][3]=a4.w;
        buf[1][4]=b4.x; buf[1][5]=b4.y; buf[1][6]=b4.z; buf[1][7]=b4.w;
    }
    curL = __shfl_up_sync(FULL, buf[0][7], 1);   curL = l0  ? FINF : curL;
    curR = __shfl_down_sync(FULL, buf[0][0], 1); curR = l31 ? FINF : curR;

    // ---- carried packed masks from row R0-1 ----
    if (R0 > 0) {
        float pr[8];
        float4 a4 = *(const float4*)(base - 256);
        float4 b4 = *(const float4*)(base - 256 + 4);
        pr[0]=a4.x; pr[1]=a4.y; pr[2]=a4.z; pr[3]=a4.w;
        pr[4]=b4.x; pr[5]=b4.y; pr[6]=b4.z; pr[7]=b4.w;
        float prL = __shfl_up_sync(FULL, pr[7], 1);   prL = l0  ? FINF : prL;
        float prR = __shfl_down_sync(FULL, pr[0], 1); prR = l31 ? FINF : prR;
        // PV[c] = cur[c] > pr[c]   (clean: summed as GU)
        PV0 = pack01(pr[0]-buf[0][0], pr[1]-buf[0][1], pr[2]-buf[0][2], pr[3]-buf[0][3]);
        PV1 = pack01(pr[4]-buf[0][4], pr[5]-buf[0][5], pr[6]-buf[0][6], pr[7]-buf[0][7]);
        // PD[c] = cur[c+1] > pr[c] (c=7: curR)  (FF-form: LOP3-only)
        PD0 = packFF(pr[0]-buf[0][1], pr[1]-buf[0][2], pr[2]-buf[0][3], pr[3]-buf[0][4]);
        PD1 = packFF(pr[4]-buf[0][5], pr[5]-buf[0][6], pr[6]-buf[0][7], pr[7]-curR);
        // PA[c] = cur[c-1] > pr[c] (c=0 byte unused)  (FF-form)
        PA0 = packFF(1.0f,            pr[1]-buf[0][0], pr[2]-buf[0][1], pr[3]-buf[0][2]);
        PA1 = packFF(pr[4]-buf[0][3], pr[5]-buf[0][4], pr[6]-buf[0][5], pr[7]-buf[0][6]);
        pdm1b = signbitFF(prL - buf[0][0]);   // cur[0] > prL
        pa8b  = signbitFF(prR - buf[0][7]);   // cur[7] > prR
    } else {
        PV0 = PV1 = PD0 = PD1 = PA0 = PA1 = 0u;
        pdm1b = 0u; pa8b = 0u;
    }

    // ---- main loop: explicit rotation, all indices compile-time ----
#pragma unroll
    for (int i = 0; i < RPW; ++i) {
        const int i0 = i % 3;          // current row
        const int i1 = (i + 1) % 3;    // down row
        const int i2 = (i + 2) % 3;    // prefetch slot

        float dnL = __shfl_up_sync(FULL, buf[i1][7], 1);   dnL = l0  ? FINF : dnL;
        float dnR = __shfl_down_sync(FULL, buf[i1][0], 1); dnR = l31 ? FINF : dnR;

        // prefetch row R0+i+2 into buf[i2]
        if (i + 2 < RPW) {
            const float* p = base + (i + 2) * 256;
            float4 a4 = *(const float4*)(p);
            float4 b4 = *(const float4*)(p + 4);
            buf[i2][0]=a4.x; buf[i2][1]=a4.y; buf[i2][2]=a4.z; buf[i2][3]=a4.w;
            buf[i2][4]=b4.x; buf[i2][5]=b4.y; buf[i2][6]=b4.z; buf[i2][7]=b4.w;
        } else if (i + 2 == RPW) {
            if (!lastStrip) {
                const float* p = base + (i + 2) * 256;
                float4 a4 = *(const float4*)(p);
                float4 b4 = *(const float4*)(p + 4);
                buf[i2][0]=a4.x; buf[i2][1]=a4.y; buf[i2][2]=a4.z; buf[i2][3]=a4.w;
                buf[i2][4]=b4.x; buf[i2][5]=b4.y; buf[i2][6]=b4.z; buf[i2][7]=b4.w;
            } else {
#pragma unroll
                for (int c = 0; c < 8; ++c) buf[i2][c] = FINF;
            }
        }

        // ---- packed compare masks (byte c = pixel c) ----
        // NH[c] = right > cur[c]   (clean: summed, carried as GL source)
        const unsigned NH0 = pack01(buf[i0][0]-buf[i0][1], buf[i0][1]-buf[i0][2],
                                    buf[i0][2]-buf[i0][3], buf[i0][3]-buf[i0][4]);
        const unsigned NH1 = pack01(buf[i0][4]-buf[i0][5], buf[i0][5]-buf[i0][6],
                                    buf[i0][6]-buf[i0][7], buf[i0][7]-curR);
        // V[c] = dn[c] > cur[c]    (clean: summed now, GU next row)
        const unsigned V0 = pack01(buf[i0][0]-buf[i1][0], buf[i0][1]-buf[i1][1],
                                   buf[i0][2]-buf[i1][2], buf[i0][3]-buf[i1][3]);
        const unsigned V1 = pack01(buf[i0][4]-buf[i1][4], buf[i0][5]-buf[i1][5],
                                   buf[i0][6]-buf[i1][6], buf[i0][7]-buf[i1][7]);
        // Dm[c] = dn[c+1] > cur[c]  (c=7: dnR)   (FF-form)
        const unsigned D0 = packFF(buf[i0][0]-buf[i1][1], buf[i0][1]-buf[i1][2],
                                   buf[i0][2]-buf[i1][3], buf[i0][3]-buf[i1][4]);
        const unsigned D1 = packFF(buf[i0][4]-buf[i1][5], buf[i0][5]-buf[i1][6],
                                   buf[i0][6]-buf[i1][7], buf[i0][7]-dnR);
        // Am[c] = dn[c-1] > cur[c]  (c=0: dnL)   (FF-form)
        const unsigned A0 = packFF(buf[i0][0]-dnL,        buf[i0][1]-buf[i1][0],
                                   buf[i0][2]-buf[i1][1], buf[i0][3]-buf[i1][2]);
        const unsigned A1 = packFF(buf[i0][4]-buf[i1][3], buf[i0][5]-buf[i1][4],
                                   buf[i0][6]-buf[i1][5], buf[i0][7]-buf[i1][6]);

        const unsigned hm1b = signbit01(curL - buf[i0][0]);   // clean (summed via GL)

        // ---- shifted vectors (boundary bytes via PRMT) ----
        const unsigned GL0  = __byte_perm(NH0, hm1b,  0x2104);   // clean
        const unsigned GL1  = __byte_perm(NH0, NH1,   0x6543);   // clean
        const unsigned GUL0 = __byte_perm(PD0, pdm1b, 0x2104);   // FF
        const unsigned GUL1 = __byte_perm(PD0, PD1,   0x6543);   // FF
        const unsigned GUR0 = __byte_perm(PA0, PA1,   0x4321);   // FF
        const unsigned GUR1 = __byte_perm(PA1, pa8b,  0x4321);   // FF
        const unsigned GU0  = PV0, GU1 = PV1;                    // clean

        // ---- packed signed-byte w:
        //      w = nh + v + s1+s2+s3+s4 - gl - gu - 1
        //      W128 byte = w + 128 (borrowless, bias 127); ^0x80 -> signed byte
        unsigned Ws0, Ws1;
        {
            const unsigned s1 = GL0 & GU0 & GUL0;
            const unsigned s2 = GU0 & GUR0 & ~NH0;
            const unsigned s3 = GL0 & ~V0 & ~A0;
            const unsigned t  = ONE & ~NH0 & ~V0;
            const unsigned s4 = t & ~D0;
            const unsigned T1 = NH0 + V0 + s1;
            const unsigned T2 = s2 + s3 + s4;
            Ws0 = (T1 + T2 + (0x7F7F7F7Fu - GL0 - GU0)) ^ 0x80808080u;
        }
        {
            const unsigned s1 = GL1 & GU1 & GUL1;
            const unsigned s2 = GU1 & GUR1 & ~NH1;
            const unsigned s3 = GL1 & ~V1 & ~A1;
            const unsigned t  = ONE & ~NH1 & ~V1;
            const unsigned s4 = t & ~D1;
            const unsigned T1 = NH1 + V1 + s1;
            const unsigned T2 = s2 + s3 + s4;
            Ws1 = (T1 + T2 + (0x7F7F7F7Fu - GL1 - GU1)) ^ 0x80808080u;
        }

        // ---- scatter: ONE sign-extending prmt per pixel (w directly), REDS ----
#pragma unroll
        for (int c = 0; c < 8; ++c) {
            const unsigned Wj = (c < 4) ? Ws0 : Ws1;
            const int w = sext_byte(Wj, 0x8880 + 0x1111 * (c & 3));
            const float m = buf[i0][c];
            const unsigned bits = __float_as_uint(__fmaf_ru(m, 31.0f, 8388608.0f));
            atomicAdd((int*)(hb + bits * 256u), w);
        }

        // ---- carries for next row ----
        PV0 = V0; PV1 = V1;
        PD0 = D0; PD1 = D1;
        PA0 = A0; PA1 = A1;
        pdm1b = signbitFF(curL - buf[i1][0]);   // dn[0] > curL
        pa8b  = signbitFF(curR - buf[i1][7]);   // dn[7] > curR
        curL = dnL; curR = dnR;
    }

    __syncthreads();

    // ---- block reduction: 2 half-sums per bin, lane-rotated (conflict-free) ----
    {
        const int b = tid >> 1, g = tid & 1;
        int s = 0;
#pragma unroll
        for (int j = 0; j < 32; ++j)
            s += sh[(b << 6) + (g << 5) + ((j + tid) & 31)];
        s += __shfl_xor_sync(FULL, s, 1);
        if (g == 0) red[b] = s;
    }
    __syncthreads();

    // ---- inclusive cumsum + exact integer-float atomic combine across bands ----
    if (tid < 32) {
        int acc = 0;
        for (int k = 0; k <= tid; ++k) acc += red[k];
        atomicAdd(&out[img * 32 + tid], (float)acc);
    }
}

extern "C" void kernel_launch(void* const* d_in, const int* in_sizes, int n_in,
                              void* d_out, int out_size) {
    const float* x = (const float*)d_in[0];
    float* out = (float*)d_out;
    ecc_zero<<<24, 256>>>(out);
    ecc_main<<<3072, TPB>>>(x, out);
}